// round 6
// baseline (speedup 1.0000x reference)
#include <cuda_runtime.h>
#include <math.h>

// Problem constants
#define NQ     512
#define NROWS  4096
#define VPR    256
#define DIM    128
#define KSEL   32
#define MEMSZ  (NROWS*VPR)

// Output layout (flat float32 concat, reference tuple order)
#define OFF_VAL   0LL                       // [512,32,128]
#define OFF_ENT   2097152LL                 // [512,32]
#define OFF_GID   2113536LL                 // [512,32]
#define OFF_SC    2129920LL                 // [512,32]
#define OFF_MASK  2146304LL                 // [512,32]
#define OFF_NDIS  2162688LL                 // scalar
#define OFF_ATTN  2162689LL                 // [512,32]

// smem layout for score kernel
#define QS_STRIDE 129                       // scalar reads -> bank = (q + kk) % 32, conflict-free
#define KS_STRIDE 260                       // 16B-aligned rows, vector reads conflict-free
#define SMEM_BYTES ((DIM*QS_STRIDE + DIM*KS_STRIDE) * 4)

// Scratch (no allocation allowed -> device globals)
__device__ float          g_rowmax[(size_t)NQ*NROWS];   // 8 MB
__device__ unsigned char  g_rowarg[(size_t)NQ*NROWS];   // 2 MB
__device__ int            g_toprow[NQ*KSEL];
__device__ float          g_topscore[NQ*KSEL];
__device__ int            g_qdis[NQ];

// ---------------------------------------------------------------------------
// Pass 1: fused scores + per-row max/argmax.
// CTA = (row, qtile of 128). Tile: 128q x 256keys x K=128, fp32 via fma.rn.f32x2.
// ---------------------------------------------------------------------------
__global__ void __launch_bounds__(256, 1)
score_kernel(const float* __restrict__ queries, const float* __restrict__ keys)
{
    extern __shared__ float smem[];
    float* Qs = smem;                        // [128][129], natural [q][k]
    float* Ks = smem + DIM * QS_STRIDE;      // [128][260], transposed [k][n]

    const int tid = threadIdx.x;
    const int row = blockIdx.x;
    const int q0  = blockIdx.y * 128;

    // ---- load Q tile (coalesced float4 reads, scalar smem writes) ----
    {
        const float4* qg = reinterpret_cast<const float4*>(queries + (size_t)q0 * DIM);
        #pragma unroll
        for (int idx = tid; idx < 128 * 32; idx += 256) {
            int q = idx >> 5, d4 = idx & 31;
            float4 v = qg[q * 32 + d4];
            float* p = Qs + q * QS_STRIDE + 4 * d4;
            p[0] = v.x; p[1] = v.y; p[2] = v.z; p[3] = v.w;
        }
    }
    // ---- load K tile transposed (coalesced reads: 4 rows x 128B per warp step) ----
    {
        const int lane = tid & 31, w = tid >> 5;
        const float4* kg = reinterpret_cast<const float4*>(keys + (size_t)row * VPR * DIM);
        #pragma unroll
        for (int g = 0; g < 8; ++g) {
            int n = w * 32 + g * 4 + (lane >> 3);
            #pragma unroll
            for (int it = 0; it < 4; ++it) {
                int d4 = (lane & 7) + 8 * it;
                float4 v = kg[n * 32 + d4];
                Ks[(4 * d4 + 0) * KS_STRIDE + n] = v.x;
                Ks[(4 * d4 + 1) * KS_STRIDE + n] = v.y;
                Ks[(4 * d4 + 2) * KS_STRIDE + n] = v.z;
                Ks[(4 * d4 + 3) * KS_STRIDE + n] = v.w;
            }
        }
    }
    __syncthreads();

    const int tn = tid & 15;      // key group
    const int tq = tid >> 4;      // query group
    const int qb = tq * 8;

    // 8 queries x 16 keys as 8 key-pairs (packed f32x2)
    unsigned long long acc[8][8];
    #pragma unroll
    for (int i = 0; i < 8; ++i)
        #pragma unroll
        for (int p = 0; p < 8; ++p) acc[i][p] = 0ull;

    #pragma unroll 4
    for (int kk = 0; kk < DIM; ++kk) {
        unsigned long long qp[8];
        #pragma unroll
        for (int i = 0; i < 8; ++i) {
            float qv = Qs[(qb + i) * QS_STRIDE + kk];
            asm("mov.b64 %0, {%1, %1};" : "=l"(qp[i]) : "f"(qv));
        }
        const unsigned long long* krow =
            reinterpret_cast<const unsigned long long*>(Ks + kk * KS_STRIDE);
        #pragma unroll
        for (int c = 0; c < 4; ++c) {
            // keys n = 64c + 4tn .. +3 (16B-aligned, conflict-free per phase)
            ulonglong2 kp = *reinterpret_cast<const ulonglong2*>(krow + 32 * c + 2 * tn);
            #pragma unroll
            for (int i = 0; i < 8; ++i) {
                asm("fma.rn.f32x2 %0, %1, %2, %0;"
                    : "+l"(acc[i][2 * c + 0]) : "l"(qp[i]), "l"(kp.x));
                asm("fma.rn.f32x2 %0, %1, %2, %0;"
                    : "+l"(acc[i][2 * c + 1]) : "l"(qp[i]), "l"(kp.y));
            }
        }
    }
    __syncthreads();   // done reading smem; reuse Qs region for reduction

    float* pv = smem;                                  // [128][16] partial max
    int*   pn = reinterpret_cast<int*>(smem + 128*16); // [128][16] partial argmax
    #pragma unroll
    for (int i = 0; i < 8; ++i) {
        float bv = -3.4e38f; int bn = 0;
        #pragma unroll
        for (int c = 0; c < 4; ++c) {
            #pragma unroll
            for (int h = 0; h < 2; ++h) {
                float lo, hi;
                asm("mov.b64 {%0, %1}, %2;" : "=f"(lo), "=f"(hi) : "l"(acc[i][2*c+h]));
                int n = 64 * c + 4 * tn + 2 * h;   // ascending within thread
                if (lo > bv) { bv = lo; bn = n; }
                if (hi > bv) { bv = hi; bn = n + 1; }
            }
        }
        pv[(qb + i) * 16 + tn] = bv;
        pn[(qb + i) * 16 + tn] = bn;
    }
    __syncthreads();

    if (tid < 128) {
        float bv = -3.4e38f; int bn = VPR;
        #pragma unroll
        for (int t = 0; t < 16; ++t) {
            float v = pv[tid * 16 + t]; int n = pn[tid * 16 + t];
            if (v > bv || (v == bv && n < bn)) { bv = v; bn = n; }  // tie -> lowest idx (jnp.argmax)
        }
        int gq = q0 + tid;
        g_rowmax[(size_t)gq * NROWS + row] = bv;
        g_rowarg[(size_t)gq * NROWS + row] = (unsigned char)bn;
    }
}

// ---------------------------------------------------------------------------
// Pass 2: top-32 rows per query, descending (== reference top-64 then sel[0..31]).
// ---------------------------------------------------------------------------
__global__ void __launch_bounds__(256)
topk_kernel()
{
    __shared__ float sv[NROWS];
    __shared__ float rv[256];
    __shared__ int   ri[256];
    const int q = blockIdx.x, tid = threadIdx.x;

    const float* src = g_rowmax + (size_t)q * NROWS;
    for (int r = tid; r < NROWS; r += 256) sv[r] = src[r];
    __syncthreads();

    for (int it = 0; it < KSEL; ++it) {
        float bv = -3.4e38f; int bi = NROWS;
        #pragma unroll
        for (int t = 0; t < 16; ++t) {
            int r = tid * 16 + t;
            float v = sv[r];
            if (v > bv) { bv = v; bi = r; }     // ascending scan -> tie keeps lowest
        }
        rv[tid] = bv; ri[tid] = bi;
        __syncthreads();
        for (int s = 128; s > 0; s >>= 1) {
            if (tid < s) {
                float v2 = rv[tid + s]; int i2 = ri[tid + s];
                if (v2 > rv[tid] || (v2 == rv[tid] && i2 < ri[tid])) { rv[tid] = v2; ri[tid] = i2; }
            }
            __syncthreads();
        }
        if (tid == 0) {
            int r = ri[0];
            g_toprow[q * KSEL + it]   = r;
            g_topscore[q * KSEL + it] = rv[0];
            sv[r] = -3.4e38f;
        }
        __syncthreads();
    }
}

// ---------------------------------------------------------------------------
// Pass 3: gathers, mask, softmax, output writes (one block per query).
// ---------------------------------------------------------------------------
__device__ __forceinline__ void put(float* out, long long off, long long lim, float v) {
    if (off < lim) out[off] = v;
}

__global__ void __launch_bounds__(128)
finalize_kernel(const float* __restrict__ values, const int* __restrict__ mem_ids,
                const int* __restrict__ ent_ids, const int* __restrict__ text_ids,
                float* __restrict__ out, long long lim)
{
    __shared__ int sid[KSEL];
    const int q = blockIdx.x, tid = threadIdx.x;

    if (tid < KSEL) {   // exactly warp 0
        int   row = g_toprow[q * KSEL + tid];
        float sc  = g_topscore[q * KSEL + tid];
        int   arg = g_rowarg[(size_t)q * NROWS + row];
        int   id  = row * VPR + arg;
        sid[tid] = id;

        int   m  = (mem_ids[id] == text_ids[q]) ? 1 : 0;
        float ms = sc - (float)m * 1e10f;

        float mx = ms;
        #pragma unroll
        for (int o = 16; o > 0; o >>= 1) mx = fmaxf(mx, __shfl_xor_sync(0xffffffffu, mx, o));
        float e = expf(ms - mx);
        float ssum = e;
        #pragma unroll
        for (int o = 16; o > 0; o >>= 1) ssum += __shfl_xor_sync(0xffffffffu, ssum, o);
        float w = e / ssum;

        int cnt = m;
        #pragma unroll
        for (int o = 16; o > 0; o >>= 1) cnt += __shfl_xor_sync(0xffffffffu, cnt, o);
        if (tid == 0) g_qdis[q] = cnt;

        long long base = (long long)q * KSEL + tid;
        put(out, OFF_ENT  + base, lim, (float)ent_ids[id]);
        put(out, OFF_GID  + base, lim, (float)id);
        put(out, OFF_SC   + base, lim, sc);
        put(out, OFF_MASK + base, lim, (float)m);
        put(out, OFF_ATTN + base, lim, w);
    }
    __syncthreads();

    // top_values gather: 32 rows x 128 floats, coalesced
    for (int j = 0; j < KSEL; ++j) {
        int id = sid[j];
        long long o = OFF_VAL + ((long long)(q * KSEL + j)) * DIM + tid;
        if (o < lim) out[o] = values[(size_t)id * DIM + tid];
    }
}

// ---------------------------------------------------------------------------
// Pass 4: n_disallowed scalar
// ---------------------------------------------------------------------------
__global__ void __launch_bounds__(512)
ndis_kernel(float* __restrict__ out, long long lim)
{
    __shared__ int s[512];
    int t = threadIdx.x;
    s[t] = g_qdis[t];
    __syncthreads();
    for (int st = 256; st > 0; st >>= 1) {
        if (t < st) s[t] += s[t + st];
        __syncthreads();
    }
    if (t == 0 && OFF_NDIS < lim) out[OFF_NDIS] = (float)s[0];
}

// ---------------------------------------------------------------------------
extern "C" void kernel_launch(void* const* d_in, const int* in_sizes, int n_in,
                              void* d_out, int out_size)
{
    const float* queries  = (const float*)d_in[0];
    const float* keys     = (const float*)d_in[1];
    const int*   mem_ids  = (const int*)d_in[2];
    const int*   ent_ids  = (const int*)d_in[3];
    const float* values   = (const float*)d_in[4];
    const int*   text_ids = (const int*)d_in[5];
    float* out = (float*)d_out;
    long long lim = (long long)out_size;

    cudaFuncSetAttribute(score_kernel, cudaFuncAttributeMaxDynamicSharedMemorySize, SMEM_BYTES);

    dim3 g1(NROWS, NQ / 128);
    score_kernel<<<g1, 256, SMEM_BYTES>>>(queries, keys);
    topk_kernel<<<NQ, 256>>>();
    finalize_kernel<<<NQ, 128>>>(values, mem_ids, ent_ids, text_ids, out, lim);
    ndis_kernel<<<1, 512>>>(out, lim);
}

// round 8
// speedup vs baseline: 1.2952x; 1.2952x over previous
#include <cuda_runtime.h>
#include <math.h>
#include <stdint.h>

// Problem constants
#define NQ     512
#define NROWS  4096
#define VPR    256
#define DIM    128
#define KSEL   32

// Output layout (flat float32 concat, reference tuple order)
#define OFF_VAL   0LL
#define OFF_ENT   2097152LL
#define OFF_GID   2113536LL
#define OFF_SC    2129920LL
#define OFF_MASK  2146304LL
#define OFF_NDIS  2162688LL
#define OFF_ATTN  2162689LL

// ---------------------------------------------------------------------------
// helpers
// ---------------------------------------------------------------------------
__device__ __forceinline__ uint32_t smem_u32(const void* p) {
    uint32_t a;
    asm("{ .reg .u64 t; cvta.to.shared.u64 t, %1; cvt.u32.u64 %0, t; }" : "=r"(a) : "l"(p));
    return a;
}

#define LDSM_X4(r0, r1, r2, r3, addr) \
    asm volatile("ldmatrix.sync.aligned.m8n8.x4.shared.b16 {%0,%1,%2,%3}, [%4];" \
        : "=r"(r0), "=r"(r1), "=r"(r2), "=r"(r3) : "r"(addr))

#define MMA16816(d, a, b) \
    asm volatile("mma.sync.aligned.m16n8k16.row.col.f32.bf16.bf16.f32 " \
        "{%0,%1,%2,%3}, {%4,%5,%6,%7}, {%8,%9}, {%0,%1,%2,%3};" \
        : "+f"((d)[0]), "+f"((d)[1]), "+f"((d)[2]), "+f"((d)[3]) \
        : "r"((a)[0]), "r"((a)[1]), "r"((a)[2]), "r"((a)[3]), \
          "r"((b)[0]), "r"((b)[1]))

// bf16 3-way split: a = lo(u0)+lo(u1)+lo(u2) to ~24 mantissa bits
__device__ __forceinline__ uint32_t pack_bf16x2(float lo, float hi) {
    uint32_t r;
    asm("cvt.rn.bf16x2.f32 %0, %1, %2;" : "=r"(r) : "f"(hi), "f"(lo));
    return r;
}
__device__ __forceinline__ float bflo(uint32_t u) { return __uint_as_float(u << 16); }
__device__ __forceinline__ float bfhi(uint32_t u) { return __uint_as_float(u & 0xffff0000u); }
__device__ __forceinline__ void split3(float a, float b, uint32_t& u0, uint32_t& u1, uint32_t& u2) {
    u0 = pack_bf16x2(a, b);
    a -= bflo(u0); b -= bfhi(u0);
    u1 = pack_bf16x2(a, b);
    a -= bflo(u1); b -= bfhi(u1);
    u2 = pack_bf16x2(a, b);
}

// ---------------------------------------------------------------------------
// Scratch
// ---------------------------------------------------------------------------
__device__ unsigned long long g_rowpack[(size_t)NQ*NROWS]; // low32 = score bits, high32 = argmax
__device__ int    g_toprow[NQ*KSEL];
__device__ float  g_topscore[NQ*KSEL];
__device__ int    g_qdis[NQ];

// ---------------------------------------------------------------------------
// Pass 1: HMMA (mma.sync bf16) with bf16x3 split, 6 cross terms, term-grouped
// fragment reuse. CTA = 256 thr; tile M=128 q x N=64 keys x K=128 per split.
// smem: Q splits 3x32KB resident + B double buffer 2x(3x16KB).
// ---------------------------------------------------------------------------
#define GROUPS 37
#define Q_SPL_SZ 32768
#define B_SPL_SZ 16384
#define B_BUF_SZ (3*B_SPL_SZ)
#define B_BASE   (3*Q_SPL_SZ)
#define SMEM_SCORE (B_BASE + 2*B_BUF_SZ)   // 196608

__global__ void __launch_bounds__(256, 1)
score_kernel_mma(const float* __restrict__ queries, const float* __restrict__ keys)
{
    extern __shared__ __align__(128) char sm[];
    const uint32_t sb = smem_u32(sm);
    __shared__ float xv[2][128];
    __shared__ int   xn[2][128];

    const int tid  = threadIdx.x;
    const int wid  = tid >> 5;
    const int lane = tid & 31;
    const int qt   = blockIdx.x & 3;
    const int rg   = blockIdx.x >> 2;
    const int q0   = qt * 128;

    const int wy = wid >> 1;            // m-warp (0..3)
    const int wn = wid & 1;             // n-warp (0..1)
    const int mbase = wy * 32;
    const int nbase = wn * 32;

    // ---- Q prologue: fp32 -> bf16x3 -> swizzled smem [q][k] ----
    {
        int q = tid >> 1, h = tid & 1;
        const float4* qp = reinterpret_cast<const float4*>(
            queries + (size_t)(q0 + q) * DIM + h * 64);
        #pragma unroll
        for (int jj = 0; jj < 8; ++jj) {
            float4 x = qp[2*jj], y = qp[2*jj+1];
            uint4 s0, s1, s2;
            split3(x.x, x.y, s0.x, s1.x, s2.x);
            split3(x.z, x.w, s0.y, s1.y, s2.y);
            split3(y.x, y.y, s0.z, s1.z, s2.z);
            split3(y.z, y.w, s0.w, s1.w, s2.w);
            int cb = h * 8 + jj;
            uint32_t o = (uint32_t)q * 256u + (uint32_t)((cb ^ (q & 7)) << 4);
            *reinterpret_cast<uint4*>(sm + 0*Q_SPL_SZ + o) = s0;
            *reinterpret_cast<uint4*>(sm + 1*Q_SPL_SZ + o) = s1;
            *reinterpret_cast<uint4*>(sm + 2*Q_SPL_SZ + o) = s2;
        }
    }

    const int nrows = (NROWS - rg + GROUPS - 1) / GROUPS;
    const int NT = nrows * 4;

    // convert thread mapping: key n = tid>>2 (0..63), part p = tid&3 (32 dims)
    const int cvn = tid >> 2;
    const int cvp = tid & 3;

    // ---- convert tile 0 into buf 0 ----
    {
        const float4* kg = reinterpret_cast<const float4*>(
            keys + ((size_t)rg * VPR + (size_t)cvn) * DIM + cvp * 32);
        float4 st[8];
        #pragma unroll
        for (int j = 0; j < 8; ++j) st[j] = kg[j];
        char* bb = sm + B_BASE;
        #pragma unroll
        for (int jj = 0; jj < 4; ++jj) {
            float4 x = st[2*jj], y = st[2*jj+1];
            uint4 s0, s1, s2;
            split3(x.x, x.y, s0.x, s1.x, s2.x);
            split3(x.z, x.w, s0.y, s1.y, s2.y);
            split3(y.x, y.y, s0.z, s1.z, s2.z);
            split3(y.z, y.w, s0.w, s1.w, s2.w);
            int cb = cvp * 4 + jj;
            uint32_t o = (uint32_t)cvn * 256u + (uint32_t)((cb ^ (cvn & 7)) << 4);
            *reinterpret_cast<uint4*>(bb + 0*B_SPL_SZ + o) = s0;
            *reinterpret_cast<uint4*>(bb + 1*B_SPL_SZ + o) = s1;
            *reinterpret_cast<uint4*>(bb + 2*B_SPL_SZ + o) = s2;
        }
    }
    __syncthreads();

    // ldmatrix lane address invariants
    const uint32_t aoff = (uint32_t)(mbase + (lane & 15)) * 256u;
    const uint32_t boff = (uint32_t)(nbase + ((lane & 7) | ((lane >> 4) << 3))) * 256u;
    const int axor = lane & 7;
    const int acq  = lane >> 4;          // A col half select
    const int bcq  = (lane >> 3) & 1;    // B col half select

    float run_v[4]; int run_n[4];

    for (int tt = 0; tt < NT; ++tt) {
        const int row = rg + GROUPS * (tt >> 2);
        const int qtr = tt & 3;
        const int buf = tt & 1;

        // ---- prefetch next tile's keys (clamped on last) ----
        const int tn   = (tt + 1 < NT) ? tt + 1 : tt;
        const int rown = rg + GROUPS * (tn >> 2);
        const int qtrn = tn & 3;
        float4 st[8];
        {
            const float4* kg = reinterpret_cast<const float4*>(
                keys + ((size_t)rown * VPR + (size_t)qtrn * 64 + (size_t)cvn) * DIM + cvp * 32);
            #pragma unroll
            for (int j = 0; j < 8; ++j) st[j] = kg[j];
        }

        // ---- compute: 8 k-positions x (12 LDSM.x4 + 48 HMMA) ----
        float acc[2][4][4];
        #pragma unroll
        for (int mt = 0; mt < 2; ++mt)
            #pragma unroll
            for (int nt = 0; nt < 4; ++nt)
                #pragma unroll
                for (int r = 0; r < 4; ++r) acc[mt][nt][r] = 0.f;

        const uint32_t bbase = sb + B_BASE + (uint32_t)buf * B_BUF_SZ;

        #pragma unroll 2
        for (int kp = 0; kp < 8; ++kp) {
            uint32_t a[3][2][4], b[3][4][2];
            const uint32_t aswz = (uint32_t)(((kp * 2 + acq) ^ axor) << 4);
            const uint32_t bswz = (uint32_t)(((kp * 2 + bcq) ^ axor) << 4);
            #pragma unroll
            for (int s = 0; s < 3; ++s) {
                #pragma unroll
                for (int mt = 0; mt < 2; ++mt) {
                    uint32_t ad = sb + (uint32_t)s * Q_SPL_SZ + aoff + (uint32_t)mt * 4096u + aswz;
                    LDSM_X4(a[s][mt][0], a[s][mt][1], a[s][mt][2], a[s][mt][3], ad);
                }
                #pragma unroll
                for (int h = 0; h < 2; ++h) {
                    uint32_t r0, r1, r2, r3;
                    uint32_t bd = bbase + (uint32_t)s * B_SPL_SZ + boff + (uint32_t)h * 4096u + bswz;
                    LDSM_X4(r0, r1, r2, r3, bd);
                    b[s][2*h  ][0] = r0; b[s][2*h  ][1] = r1;
                    b[s][2*h+1][0] = r2; b[s][2*h+1][1] = r3;
                }
            }
            const int tas[6] = {0, 0, 1, 1, 2, 0};
            const int tbs[6] = {0, 1, 0, 1, 0, 2};
            #pragma unroll
            for (int term = 0; term < 6; ++term) {
                #pragma unroll
                for (int mt = 0; mt < 2; ++mt)
                    #pragma unroll
                    for (int nt = 0; nt < 4; ++nt)
                        MMA16816(acc[mt][nt], a[tas[term]][mt], b[tbs[term]][nt]);
            }
        }

        // ---- convert prefetched keys into buf^1 ----
        {
            char* bb = sm + B_BASE + (buf ^ 1) * B_BUF_SZ;
            #pragma unroll
            for (int jj = 0; jj < 4; ++jj) {
                float4 x = st[2*jj], y = st[2*jj+1];
                uint4 s0, s1, s2;
                split3(x.x, x.y, s0.x, s1.x, s2.x);
                split3(x.z, x.w, s0.y, s1.y, s2.y);
                split3(y.x, y.y, s0.z, s1.z, s2.z);
                split3(y.z, y.w, s0.w, s1.w, s2.w);
                int cb = cvp * 4 + jj;
                uint32_t o = (uint32_t)cvn * 256u + (uint32_t)((cb ^ (cvn & 7)) << 4);
                *reinterpret_cast<uint4*>(bb + 0*B_SPL_SZ + o) = s0;
                *reinterpret_cast<uint4*>(bb + 1*B_SPL_SZ + o) = s1;
                *reinterpret_cast<uint4*>(bb + 2*B_SPL_SZ + o) = s2;
            }
        }
        __syncthreads();

        // ---- epilogue: per-query running max/argmax over this tile's 64 keys ----
        #pragma unroll
        for (int mt = 0; mt < 2; ++mt) {
            #pragma unroll
            for (int rh = 0; rh < 2; ++rh) {
                const int sl = mt * 2 + rh;
                float v = -3.4e38f; int id = 0;
                #pragma unroll
                for (int nt = 0; nt < 4; ++nt) {
                    #pragma unroll
                    for (int hh = 0; hh < 2; ++hh) {
                        float x = acc[mt][nt][rh * 2 + hh];
                        int kid = qtr * 64 + nbase + nt * 8 + (lane & 3) * 2 + hh;
                        if (x > v) { v = x; id = kid; }   // ascending kid -> tie keeps lowest
                    }
                }
                #pragma unroll
                for (int o = 1; o <= 2; o <<= 1) {
                    float v2 = __shfl_xor_sync(0xffffffffu, v, o);
                    int   i2 = __shfl_xor_sync(0xffffffffu, id, o);
                    if (v2 > v || (v2 == v && i2 < id)) { v = v2; id = i2; }
                }
                if (qtr == 0) { run_v[sl] = v; run_n[sl] = id; }
                else if (v > run_v[sl] || (v == run_v[sl] && id < run_n[sl])) {
                    run_v[sl] = v; run_n[sl] = id;
                }
            }
        }

        if (qtr == 3) {
            if ((lane & 3) == 0) {
                #pragma unroll
                for (int mt = 0; mt < 2; ++mt)
                    #pragma unroll
                    for (int rh = 0; rh < 2; ++rh) {
                        int r = mbase + mt * 16 + rh * 8 + (lane >> 2);
                        xv[wn][r] = run_v[mt * 2 + rh];
                        xn[wn][r] = run_n[mt * 2 + rh];
                    }
            }
            __syncthreads();
            if (tid < 128) {
                float v0 = xv[0][tid]; int n0 = xn[0][tid];
                float v1 = xv[1][tid]; int n1 = xn[1][tid];
                float v; int n;
                if (v1 > v0 || (v1 == v0 && n1 < n0)) { v = v1; n = n1; }
                else { v = v0; n = n0; }
                g_rowpack[(size_t)(q0 + tid) * NROWS + row] =
                    ((unsigned long long)(unsigned)n << 32) | (unsigned)__float_as_uint(v);
            }
            __syncthreads();
        }
    }
}

// ---------------------------------------------------------------------------
// Pass 2: top-32 rows per query, descending (== reference top-64 then sel[:32]).
// ---------------------------------------------------------------------------
__global__ void __launch_bounds__(256)
topk_kernel()
{
    __shared__ float sv[NROWS];
    __shared__ float rv[256];
    __shared__ int   ri[256];
    const int q = blockIdx.x, tid = threadIdx.x;

    const unsigned long long* src = g_rowpack + (size_t)q * NROWS;
    for (int r = tid; r < NROWS; r += 256)
        sv[r] = __uint_as_float((unsigned)(src[r] & 0xffffffffu));
    __syncthreads();

    for (int it = 0; it < KSEL; ++it) {
        float bv = -3.4e38f; int bi = NROWS;
        #pragma unroll
        for (int t = 0; t < 16; ++t) {
            int r = tid * 16 + t;
            float v = sv[r];
            if (v > bv) { bv = v; bi = r; }
        }
        rv[tid] = bv; ri[tid] = bi;
        __syncthreads();
        for (int s = 128; s > 0; s >>= 1) {
            if (tid < s) {
                float v2 = rv[tid + s]; int i2 = ri[tid + s];
                if (v2 > rv[tid] || (v2 == rv[tid] && i2 < ri[tid])) { rv[tid] = v2; ri[tid] = i2; }
            }
            __syncthreads();
        }
        if (tid == 0) {
            int r = ri[0];
            g_toprow[q * KSEL + it]   = r;
            g_topscore[q * KSEL + it] = rv[0];
            sv[r] = -3.4e38f;
        }
        __syncthreads();
    }
}

// ---------------------------------------------------------------------------
// Pass 3: gathers, mask, softmax, output writes (one block per query).
// ---------------------------------------------------------------------------
__device__ __forceinline__ void put(float* out, long long off, long long lim, float v) {
    if (off < lim) out[off] = v;
}

__global__ void __launch_bounds__(128)
finalize_kernel(const float* __restrict__ values, const int* __restrict__ mem_ids,
                const int* __restrict__ ent_ids, const int* __restrict__ text_ids,
                float* __restrict__ out, long long lim)
{
    __shared__ int sid[KSEL];
    const int q = blockIdx.x, tid = threadIdx.x;

    if (tid < KSEL) {
        int   row = g_toprow[q * KSEL + tid];
        float sc  = g_topscore[q * KSEL + tid];
        int   arg = (int)(g_rowpack[(size_t)q * NROWS + row] >> 32);
        int   id  = row * VPR + arg;
        sid[tid] = id;

        int   m  = (mem_ids[id] == text_ids[q]) ? 1 : 0;
        float ms = sc - (float)m * 1e10f;

        float mx = ms;
        #pragma unroll
        for (int o = 16; o > 0; o >>= 1) mx = fmaxf(mx, __shfl_xor_sync(0xffffffffu, mx, o));
        float e = expf(ms - mx);
        float ssum = e;
        #pragma unroll
        for (int o = 16; o > 0; o >>= 1) ssum += __shfl_xor_sync(0xffffffffu, ssum, o);
        float w = e / ssum;

        int cnt = m;
        #pragma unroll
        for (int o = 16; o > 0; o >>= 1) cnt += __shfl_xor_sync(0xffffffffu, cnt, o);
        if (tid == 0) g_qdis[q] = cnt;

        long long base = (long long)q * KSEL + tid;
        put(out, OFF_ENT  + base, lim, (float)ent_ids[id]);
        put(out, OFF_GID  + base, lim, (float)id);
        put(out, OFF_SC   + base, lim, sc);
        put(out, OFF_MASK + base, lim, (float)m);
        put(out, OFF_ATTN + base, lim, w);
    }
    __syncthreads();

    for (int j = 0; j < KSEL; ++j) {
        int id = sid[j];
        long long o = OFF_VAL + ((long long)(q * KSEL + j)) * DIM + tid;
        if (o < lim) out[o] = values[(size_t)id * DIM + tid];
    }
}

// ---------------------------------------------------------------------------
// Pass 4: n_disallowed scalar
// ---------------------------------------------------------------------------
__global__ void __launch_bounds__(512)
ndis_kernel(float* __restrict__ out, long long lim)
{
    __shared__ int s[512];
    int t = threadIdx.x;
    s[t] = g_qdis[t];
    __syncthreads();
    for (int st = 256; st > 0; st >>= 1) {
        if (t < st) s[t] += s[t + st];
        __syncthreads();
    }
    if (t == 0 && OFF_NDIS < lim) out[OFF_NDIS] = (float)s[0];
}

// ---------------------------------------------------------------------------
extern "C" void kernel_launch(void* const* d_in, const int* in_sizes, int n_in,
                              void* d_out, int out_size)
{
    const float* queries  = (const float*)d_in[0];
    const float* keys     = (const float*)d_in[1];
    const int*   mem_ids  = (const int*)d_in[2];
    const int*   ent_ids  = (const int*)d_in[3];
    const float* values   = (const float*)d_in[4];
    const int*   text_ids = (const int*)d_in[5];
    float* out = (float*)d_out;
    long long lim = (long long)out_size;

    cudaFuncSetAttribute(score_kernel_mma, cudaFuncAttributeMaxDynamicSharedMemorySize, SMEM_SCORE);

    score_kernel_mma<<<4 * GROUPS, 256, SMEM_SCORE>>>(queries, keys);
    topk_kernel<<<NQ, 256>>>();
    finalize_kernel<<<NQ, 128>>>(values, mem_ids, ent_ids, text_ids, out, lim);
    ndis_kernel<<<1, 512>>>(out, lim);
}

// round 9
// speedup vs baseline: 1.9659x; 1.5178x over previous
#include <cuda_runtime.h>
#include <math.h>
#include <stdint.h>

// Problem constants
#define NQ     512
#define NROWS  4096
#define VPR    256
#define DIM    128
#define KSEL   32
#define CAND   64

// Output layout (flat float32 concat, reference tuple order)
#define OFF_VAL   0LL
#define OFF_ENT   2097152LL
#define OFF_GID   2113536LL
#define OFF_SC    2129920LL
#define OFF_MASK  2146304LL
#define OFF_NDIS  2162688LL
#define OFF_ATTN  2162689LL

// ---------------------------------------------------------------------------
// helpers
// ---------------------------------------------------------------------------
__device__ __forceinline__ uint32_t smem_u32(const void* p) {
    uint32_t a;
    asm("{ .reg .u64 t; cvta.to.shared.u64 t, %1; cvt.u32.u64 %0, t; }" : "=r"(a) : "l"(p));
    return a;
}

#define LDSM_X4(r0, r1, r2, r3, addr) \
    asm volatile("ldmatrix.sync.aligned.m8n8.x4.shared.b16 {%0,%1,%2,%3}, [%4];" \
        : "=r"(r0), "=r"(r1), "=r"(r2), "=r"(r3) : "r"(addr))

#define MMA16816(d, a, b) \
    asm volatile("mma.sync.aligned.m16n8k16.row.col.f32.bf16.bf16.f32 " \
        "{%0,%1,%2,%3}, {%4,%5,%6,%7}, {%8,%9}, {%0,%1,%2,%3};" \
        : "+f"((d)[0]), "+f"((d)[1]), "+f"((d)[2]), "+f"((d)[3]) \
        : "r"((a)[0]), "r"((a)[1]), "r"((a)[2]), "r"((a)[3]), \
          "r"((b)[0]), "r"((b)[1]))

__device__ __forceinline__ uint32_t pack_bf16x2(float lo, float hi) {
    uint32_t r;
    asm("cvt.rn.bf16x2.f32 %0, %1, %2;" : "=r"(r) : "f"(hi), "f"(lo));
    return r;
}

// ---------------------------------------------------------------------------
// Scratch
// ---------------------------------------------------------------------------
__device__ float g_rowmax[(size_t)NQ*NROWS];    // approx row maxima
__device__ int   g_cand[NQ*CAND];               // candidate rows per query
__device__ int   g_rowcnt[NROWS];               // queries per row
__device__ int   g_rowlist[(size_t)NROWS*NQ];   // (q<<6)|slot entries
__device__ float g_exs[NQ*CAND];                // exact candidate score
__device__ int   g_exa[NQ*CAND];                // exact candidate argmax key
__device__ int   g_qdis[NQ];

// ---------------------------------------------------------------------------
// Pass A: approximate scores, single bf16 term HMMA. CTA = 256 thr,
// tile M=128 q x N=64 keys x K=128. smem: Q 32KB + B double buffer 2x16KB.
// ---------------------------------------------------------------------------
#define GROUPS 74
#define B_BASE   32768
#define B_BUF_SZ 16384
#define SMEM_A   (B_BASE + 2*B_BUF_SZ)          // 65536

__global__ void __launch_bounds__(256)
score_approx(const float* __restrict__ queries, const float* __restrict__ keys)
{
    extern __shared__ __align__(128) char sm[];
    const uint32_t sb = smem_u32(sm);
    __shared__ float xv[2][128];

    const int tid  = threadIdx.x;
    const int wid  = tid >> 5;
    const int lane = tid & 31;
    const int qt   = blockIdx.x & 3;
    const int rg   = blockIdx.x >> 2;
    const int q0   = qt * 128;

    const int wy = wid >> 1;
    const int wn = wid & 1;
    const int mbase = wy * 32;
    const int nbase = wn * 32;

    // ---- Q prologue: fp32 -> bf16 (split0 only) -> swizzled smem ----
    {
        int q = tid >> 1, h = tid & 1;
        const float4* qp = reinterpret_cast<const float4*>(
            queries + (size_t)(q0 + q) * DIM + h * 64);
        #pragma unroll
        for (int jj = 0; jj < 8; ++jj) {
            float4 x = qp[2*jj], y = qp[2*jj+1];
            uint4 s0;
            s0.x = pack_bf16x2(x.x, x.y);
            s0.y = pack_bf16x2(x.z, x.w);
            s0.z = pack_bf16x2(y.x, y.y);
            s0.w = pack_bf16x2(y.z, y.w);
            int cb = h * 8 + jj;
            uint32_t o = (uint32_t)q * 256u + (uint32_t)((cb ^ (q & 7)) << 4);
            *reinterpret_cast<uint4*>(sm + o) = s0;
        }
    }

    const int nrows = (NROWS - rg + GROUPS - 1) / GROUPS;
    const int NT = nrows * 4;

    const int cvn = tid >> 2;
    const int cvp = tid & 3;

    // ---- convert tile 0 into buf 0 ----
    {
        const float4* kg = reinterpret_cast<const float4*>(
            keys + ((size_t)rg * VPR + (size_t)cvn) * DIM + cvp * 32);
        char* bb = sm + B_BASE;
        #pragma unroll
        for (int jj = 0; jj < 4; ++jj) {
            float4 x = kg[2*jj], y = kg[2*jj+1];
            uint4 s0;
            s0.x = pack_bf16x2(x.x, x.y);
            s0.y = pack_bf16x2(x.z, x.w);
            s0.z = pack_bf16x2(y.x, y.y);
            s0.w = pack_bf16x2(y.z, y.w);
            int cb = cvp * 4 + jj;
            uint32_t o = (uint32_t)cvn * 256u + (uint32_t)((cb ^ (cvn & 7)) << 4);
            *reinterpret_cast<uint4*>(bb + o) = s0;
        }
    }
    __syncthreads();

    const uint32_t aoff = (uint32_t)(mbase + (lane & 15)) * 256u;
    const uint32_t boff = (uint32_t)(nbase + ((lane & 7) | ((lane >> 4) << 3))) * 256u;
    const int axor = lane & 7;
    const int acq  = lane >> 4;
    const int bcq  = (lane >> 3) & 1;

    float run_v[4];

    for (int tt = 0; tt < NT; ++tt) {
        const int row = rg + GROUPS * (tt >> 2);
        const int qtr = tt & 3;
        const int buf = tt & 1;

        // prefetch next tile's keys
        const int tn   = (tt + 1 < NT) ? tt + 1 : tt;
        const int rown = rg + GROUPS * (tn >> 2);
        const int qtrn = tn & 3;
        float4 st[8];
        {
            const float4* kg = reinterpret_cast<const float4*>(
                keys + ((size_t)rown * VPR + (size_t)qtrn * 64 + (size_t)cvn) * DIM + cvp * 32);
            #pragma unroll
            for (int j = 0; j < 8; ++j) st[j] = kg[j];
        }

        float acc[2][4][4];
        #pragma unroll
        for (int mt = 0; mt < 2; ++mt)
            #pragma unroll
            for (int nt = 0; nt < 4; ++nt)
                #pragma unroll
                for (int r = 0; r < 4; ++r) acc[mt][nt][r] = 0.f;

        const uint32_t bbase = sb + B_BASE + (uint32_t)buf * B_BUF_SZ;

        #pragma unroll 2
        for (int kp = 0; kp < 8; ++kp) {
            uint32_t a[2][4], b[4][2];
            const uint32_t aswz = (uint32_t)(((kp * 2 + acq) ^ axor) << 4);
            const uint32_t bswz = (uint32_t)(((kp * 2 + bcq) ^ axor) << 4);
            #pragma unroll
            for (int mt = 0; mt < 2; ++mt) {
                uint32_t ad = sb + aoff + (uint32_t)mt * 4096u + aswz;
                LDSM_X4(a[mt][0], a[mt][1], a[mt][2], a[mt][3], ad);
            }
            #pragma unroll
            for (int h = 0; h < 2; ++h) {
                uint32_t r0, r1, r2, r3;
                uint32_t bd = bbase + boff + (uint32_t)h * 4096u + bswz;
                LDSM_X4(r0, r1, r2, r3, bd);
                b[2*h  ][0] = r0; b[2*h  ][1] = r1;
                b[2*h+1][0] = r2; b[2*h+1][1] = r3;
            }
            #pragma unroll
            for (int mt = 0; mt < 2; ++mt)
                #pragma unroll
                for (int nt = 0; nt < 4; ++nt)
                    MMA16816(acc[mt][nt], a[mt], b[nt]);
        }

        // convert prefetched keys into buf^1
        {
            char* bb = sm + B_BASE + (buf ^ 1) * B_BUF_SZ;
            #pragma unroll
            for (int jj = 0; jj < 4; ++jj) {
                float4 x = st[2*jj], y = st[2*jj+1];
                uint4 s0;
                s0.x = pack_bf16x2(x.x, x.y);
                s0.y = pack_bf16x2(x.z, x.w);
                s0.z = pack_bf16x2(y.x, y.y);
                s0.w = pack_bf16x2(y.z, y.w);
                int cb = cvp * 4 + jj;
                uint32_t o = (uint32_t)cvn * 256u + (uint32_t)((cb ^ (cvn & 7)) << 4);
                *reinterpret_cast<uint4*>(bb + o) = s0;
            }
        }
        __syncthreads();

        // epilogue: per-query running max over this tile's 64 keys
        #pragma unroll
        for (int mt = 0; mt < 2; ++mt) {
            #pragma unroll
            for (int rh = 0; rh < 2; ++rh) {
                const int sl = mt * 2 + rh;
                float v = -3.4e38f;
                #pragma unroll
                for (int nt = 0; nt < 4; ++nt) {
                    v = fmaxf(v, acc[mt][nt][rh * 2 + 0]);
                    v = fmaxf(v, acc[mt][nt][rh * 2 + 1]);
                }
                v = fmaxf(v, __shfl_xor_sync(0xffffffffu, v, 1));
                v = fmaxf(v, __shfl_xor_sync(0xffffffffu, v, 2));
                if (qtr == 0) run_v[sl] = v;
                else          run_v[sl] = fmaxf(run_v[sl], v);
            }
        }

        if (qtr == 3) {
            if ((lane & 3) == 0) {
                #pragma unroll
                for (int mt = 0; mt < 2; ++mt)
                    #pragma unroll
                    for (int rh = 0; rh < 2; ++rh) {
                        int r = mbase + mt * 16 + rh * 8 + (lane >> 2);
                        xv[wn][r] = run_v[mt * 2 + rh];
                    }
            }
            __syncthreads();
            if (tid < 128)
                g_rowmax[(size_t)(q0 + tid) * NROWS + row] = fmaxf(xv[0][tid], xv[1][tid]);
            __syncthreads();
        }
    }
}

// ---------------------------------------------------------------------------
// Pass A2: top-64 candidate rows per query by approx max (tie -> lowest row).
// ---------------------------------------------------------------------------
__global__ void __launch_bounds__(256)
top64_kernel()
{
    __shared__ float sv[NROWS];
    __shared__ float rv[256];
    __shared__ int   ri[256];
    const int q = blockIdx.x, tid = threadIdx.x;

    const float* src = g_rowmax + (size_t)q * NROWS;
    for (int r = tid; r < NROWS; r += 256) sv[r] = src[r];
    __syncthreads();

    for (int it = 0; it < CAND; ++it) {
        float bv = -3.4e38f; int bi = NROWS;
        #pragma unroll
        for (int t = 0; t < 16; ++t) {
            int r = tid * 16 + t;
            float v = sv[r];
            if (v > bv) { bv = v; bi = r; }
        }
        rv[tid] = bv; ri[tid] = bi;
        __syncthreads();
        for (int s = 128; s > 0; s >>= 1) {
            if (tid < s) {
                float v2 = rv[tid + s]; int i2 = ri[tid + s];
                if (v2 > rv[tid] || (v2 == rv[tid] && i2 < ri[tid])) { rv[tid] = v2; ri[tid] = i2; }
            }
            __syncthreads();
        }
        if (tid == 0) {
            g_cand[q * CAND + it] = ri[0];
            sv[ri[0]] = -3.4e38f;
        }
        __syncthreads();
    }
}

// ---------------------------------------------------------------------------
// zero counters + scatter candidates into per-row query lists
// ---------------------------------------------------------------------------
__global__ void zero_kernel()
{
    int i = blockIdx.x * 256 + threadIdx.x;
    if (i < NROWS) g_rowcnt[i] = 0;
}

__global__ void __launch_bounds__(64)
scatter_kernel()
{
    const int q = blockIdx.x, slot = threadIdx.x;
    int row = g_cand[q * CAND + slot];
    int idx = atomicAdd(&g_rowcnt[row], 1);
    g_rowlist[(size_t)row * NQ + idx] = (q << 6) | slot;
}

// ---------------------------------------------------------------------------
// Pass B: exact fp32 rescore. One CTA per row; row keys cached in smem,
// loop over the queries that selected this row. Exact max+argmax per (q,row).
// ---------------------------------------------------------------------------
#define KS_STR 129
#define SMEM_B (VPR * KS_STR * 4)   // 132096

__global__ void __launch_bounds__(256)
rescore_kernel(const float* __restrict__ queries, const float* __restrict__ keys)
{
    const int row = blockIdx.x;
    const int cnt = g_rowcnt[row];
    if (cnt == 0) return;

    extern __shared__ float Ks[];                 // [256][129]
    __shared__ float Qs[DIM];
    __shared__ unsigned long long red[8];

    const int tid = threadIdx.x;
    const int lane = tid & 31, wrp = tid >> 5;

    // load keys: 8192 float4s, coalesced; scalar smem writes (conflict-light)
    const float4* kg = reinterpret_cast<const float4*>(keys + (size_t)row * VPR * DIM);
    for (int idx = tid; idx < VPR * DIM / 4; idx += 256) {
        int k = idx >> 5, j = idx & 31;
        float4 v = kg[idx];
        float* p = Ks + k * KS_STR + 4 * j;
        p[0] = v.x; p[1] = v.y; p[2] = v.z; p[3] = v.w;
    }
    __syncthreads();

    for (int i = 0; i < cnt; ++i) {
        const int e = g_rowlist[(size_t)row * NQ + i];
        const int q = e >> 6, slot = e & 63;

        if (tid < DIM) Qs[tid] = queries[(size_t)q * DIM + tid];
        __syncthreads();

        // thread t: exact fp32 dot for key t
        float a0 = 0.f, a1 = 0.f;
        const float* kr = Ks + tid * KS_STR;
        #pragma unroll
        for (int d = 0; d < DIM; d += 2) {
            a0 = fmaf(kr[d],     Qs[d],     a0);
            a1 = fmaf(kr[d + 1], Qs[d + 1], a1);
        }
        float s = a0 + a1;

        // orderable pack: (score, lowest key idx on ties)
        uint32_t u = __float_as_uint(s);
        u = (u & 0x80000000u) ? ~u : (u | 0x80000000u);
        unsigned long long p = ((unsigned long long)u << 32) | (uint32_t)(~tid);
        #pragma unroll
        for (int o = 16; o > 0; o >>= 1) {
            unsigned long long p2 = __shfl_xor_sync(0xffffffffu, p, o);
            if (p2 > p) p = p2;
        }
        if (lane == 0) red[wrp] = p;
        __syncthreads();
        if (tid == 0) {
            unsigned long long b = red[0];
            #pragma unroll
            for (int w = 1; w < 8; ++w) if (red[w] > b) b = red[w];
            uint32_t ub = (uint32_t)(b >> 32);
            float sc = (ub & 0x80000000u) ? __uint_as_float(ub & 0x7FFFFFFFu)
                                          : __uint_as_float(~ub);
            g_exs[q * CAND + slot] = sc;
            g_exa[q * CAND + slot] = (int)(~(uint32_t)b & 0xFFu);
        }
        __syncthreads();
    }
}

// ---------------------------------------------------------------------------
// Pass C: exact top-32 of 64 candidates + mask/softmax/gather outputs.
// ---------------------------------------------------------------------------
__device__ __forceinline__ void put(float* out, long long off, long long lim, float v) {
    if (off < lim) out[off] = v;
}

__global__ void __launch_bounds__(128)
finalize_kernel(const float* __restrict__ values, const int* __restrict__ mem_ids,
                const int* __restrict__ ent_ids, const int* __restrict__ text_ids,
                float* __restrict__ out, long long lim)
{
    volatile __shared__ float cs[CAND];
    __shared__ int   cm[CAND];
    __shared__ int   ssel[KSEL];
    __shared__ int   sid[KSEL];
    const int q = blockIdx.x, tid = threadIdx.x;

    if (tid < CAND) {
        int row = g_cand[q * CAND + tid];
        cs[tid] = g_exs[q * CAND + tid];
        cm[tid] = (row << 6) | tid;          // row-major meta: ties -> lowest row
    }
    __syncthreads();

    if (tid < 32) {   // warp 0: 32-round selection, 2 candidates per lane
        for (int it = 0; it < KSEL; ++it) {
            float v0 = cs[tid], v1 = cs[tid + 32];
            int   m0 = cm[tid], m1 = cm[tid + 32];
            float v; int m;
            if (v1 > v0 || (v1 == v0 && m1 < m0)) { v = v1; m = m1; }
            else { v = v0; m = m0; }
            #pragma unroll
            for (int o = 16; o > 0; o >>= 1) {
                float v2 = __shfl_xor_sync(0xffffffffu, v, o);
                int   m2 = __shfl_xor_sync(0xffffffffu, m, o);
                if (v2 > v || (v2 == v && m2 < m)) { v = v2; m = m2; }
            }
            if (tid == 0) { ssel[it] = m; cs[m & 63] = -3.4e38f; }
            __syncwarp();
        }
    }
    __syncthreads();

    if (tid < KSEL) {
        int meta = ssel[tid];
        int slot = meta & 63, row = meta >> 6;
        float sc = g_exs[q * CAND + slot];
        int   arg = g_exa[q * CAND + slot];
        int   id = row * VPR + arg;
        sid[tid] = id;

        int   m  = (mem_ids[id] == text_ids[q]) ? 1 : 0;
        float ms = sc - (float)m * 1e10f;

        float mx = ms;
        #pragma unroll
        for (int o = 16; o > 0; o >>= 1) mx = fmaxf(mx, __shfl_xor_sync(0xffffffffu, mx, o));
        float e = expf(ms - mx);
        float ssum = e;
        #pragma unroll
        for (int o = 16; o > 0; o >>= 1) ssum += __shfl_xor_sync(0xffffffffu, ssum, o);
        float w = e / ssum;

        int cnt = m;
        #pragma unroll
        for (int o = 16; o > 0; o >>= 1) cnt += __shfl_xor_sync(0xffffffffu, cnt, o);
        if (tid == 0) g_qdis[q] = cnt;

        long long base = (long long)q * KSEL + tid;
        put(out, OFF_ENT  + base, lim, (float)ent_ids[id]);
        put(out, OFF_GID  + base, lim, (float)id);
        put(out, OFF_SC   + base, lim, sc);
        put(out, OFF_MASK + base, lim, (float)m);
        put(out, OFF_ATTN + base, lim, w);
    }
    __syncthreads();

    for (int j = 0; j < KSEL; ++j) {
        int id = sid[j];
        long long o = OFF_VAL + ((long long)(q * KSEL + j)) * DIM + tid;
        if (o < lim) out[o] = values[(size_t)id * DIM + tid];
    }
}

// ---------------------------------------------------------------------------
// Pass D: n_disallowed scalar
// ---------------------------------------------------------------------------
__global__ void __launch_bounds__(512)
ndis_kernel(float* __restrict__ out, long long lim)
{
    __shared__ int s[512];
    int t = threadIdx.x;
    s[t] = g_qdis[t];
    __syncthreads();
    for (int st = 256; st > 0; st >>= 1) {
        if (t < st) s[t] += s[t + st];
        __syncthreads();
    }
    if (t == 0 && OFF_NDIS < lim) out[OFF_NDIS] = (float)s[0];
}

// ---------------------------------------------------------------------------
extern "C" void kernel_launch(void* const* d_in, const int* in_sizes, int n_in,
                              void* d_out, int out_size)
{
    const float* queries  = (const float*)d_in[0];
    const float* keys     = (const float*)d_in[1];
    const int*   mem_ids  = (const int*)d_in[2];
    const int*   ent_ids  = (const int*)d_in[3];
    const float* values   = (const float*)d_in[4];
    const int*   text_ids = (const int*)d_in[5];
    float* out = (float*)d_out;
    long long lim = (long long)out_size;

    cudaFuncSetAttribute(score_approx,   cudaFuncAttributeMaxDynamicSharedMemorySize, SMEM_A);
    cudaFuncSetAttribute(rescore_kernel, cudaFuncAttributeMaxDynamicSharedMemorySize, SMEM_B);

    score_approx<<<4 * GROUPS, 256, SMEM_A>>>(queries, keys);
    top64_kernel<<<NQ, 256>>>();
    zero_kernel<<<(NROWS + 255) / 256, 256>>>();
    scatter_kernel<<<NQ, 64>>>();
    rescore_kernel<<<NROWS, 256, SMEM_B>>>(queries, keys);
    finalize_kernel<<<NQ, 128>>>(values, mem_ids, ent_ids, text_ids, out, lim);
    ndis_kernel<<<1, 512>>>(out, lim);
}

// round 10
// speedup vs baseline: 3.1110x; 1.5825x over previous
#include <cuda_runtime.h>
#include <math.h>
#include <stdint.h>

// Problem constants
#define NQ     512
#define NROWS  4096
#define VPR    256
#define DIM    128
#define KSEL   32
#define RCAP   256         // max candidates per query (threshold select collects 64..~150)

// Output layout (flat float32 concat, reference tuple order)
#define OFF_VAL   0LL
#define OFF_ENT   2097152LL
#define OFF_GID   2113536LL
#define OFF_SC    2129920LL
#define OFF_MASK  2146304LL
#define OFF_NDIS  2162688LL
#define OFF_ATTN  2162689LL

// ---------------------------------------------------------------------------
// helpers
// ---------------------------------------------------------------------------
__device__ __forceinline__ uint32_t smem_u32(const void* p) {
    uint32_t a;
    asm("{ .reg .u64 t; cvta.to.shared.u64 t, %1; cvt.u32.u64 %0, t; }" : "=r"(a) : "l"(p));
    return a;
}

#define LDSM_X4(r0, r1, r2, r3, addr) \
    asm volatile("ldmatrix.sync.aligned.m8n8.x4.shared.b16 {%0,%1,%2,%3}, [%4];" \
        : "=r"(r0), "=r"(r1), "=r"(r2), "=r"(r3) : "r"(addr))

#define MMA16816(d, a, b) \
    asm volatile("mma.sync.aligned.m16n8k16.row.col.f32.bf16.bf16.f32 " \
        "{%0,%1,%2,%3}, {%4,%5,%6,%7}, {%8,%9}, {%0,%1,%2,%3};" \
        : "+f"((d)[0]), "+f"((d)[1]), "+f"((d)[2]), "+f"((d)[3]) \
        : "r"((a)[0]), "r"((a)[1]), "r"((a)[2]), "r"((a)[3]), \
          "r"((b)[0]), "r"((b)[1]))

__device__ __forceinline__ uint32_t pack_bf16x2(float lo, float hi) {
    uint32_t r;
    asm("cvt.rn.bf16x2.f32 %0, %1, %2;" : "=r"(r) : "f"(hi), "f"(lo));
    return r;
}

// monotone orderable transform for fp32
__device__ __forceinline__ uint32_t ford(float s) {
    uint32_t u = __float_as_uint(s);
    return (u & 0x80000000u) ? ~u : (u | 0x80000000u);
}
__device__ __forceinline__ float funord(uint32_t u) {
    return (u & 0x80000000u) ? __uint_as_float(u & 0x7FFFFFFFu) : __uint_as_float(~u);
}

// mbarrier + 1D bulk DMA (sm_90 base features)
#define MBARRIER_INIT(mb, cnt) \
    asm volatile("mbarrier.init.shared.b64 [%0], %1;" :: "r"((uint32_t)(mb)), "r"((uint32_t)(cnt)) : "memory")
#define MBARRIER_EXPECT_TX(mb, bytes) \
    asm volatile("mbarrier.arrive.expect_tx.shared.b64 _, [%0], %1;" :: "r"((uint32_t)(mb)), "r"((uint32_t)(bytes)) : "memory")
#define MBARRIER_WAIT_PARITY(mb, par) do { \
    uint32_t _mb = (uint32_t)(mb); uint32_t _pa = (uint32_t)(par); uint32_t _dn; \
    asm volatile("{\n\t.reg .pred p;\n\tmbarrier.try_wait.parity.acquire.cta.shared::cta.b64 p, [%1], %2;\n\tselp.b32 %0, 1, 0, p;\n\t}" \
        : "=r"(_dn) : "r"(_mb), "r"(_pa) : "memory"); \
    if (!_dn) { \
        asm volatile("{\n\t.reg .pred P1;\n\tWL_%=:\n\tmbarrier.try_wait.parity.acquire.cta.shared::cta.b64 P1, [%0], %1, 0x989680;\n\t@P1 bra.uni WD_%=;\n\tbra.uni WL_%=;\n\tWD_%=:\n\t}" \
            :: "r"(_mb), "r"(_pa) : "memory"); \
    } \
} while (0)

__device__ __forceinline__ void bulk_g2s(uint32_t dst, const void* src, uint32_t bytes, uint32_t mbar) {
    asm volatile("cp.async.bulk.shared::cluster.global.mbarrier::complete_tx::bytes [%0], [%1], %2, [%3];"
        :: "r"(dst), "l"(src), "r"(bytes), "r"(mbar) : "memory");
}

// ---------------------------------------------------------------------------
// Scratch (device globals; no allocation allowed)
// ---------------------------------------------------------------------------
__device__ float g_rowmax[(size_t)NQ*NROWS];        // approx row maxima
__device__ int   g_cand[(size_t)NQ*RCAP];           // candidate rows per query
__device__ int   g_qcnt[NQ];                        // candidates per query
__device__ int   g_rowcnt[NROWS];                   // queries per row
__device__ int   g_rowlist[(size_t)NROWS*NQ];       // (q<<8)|slot
__device__ float g_exs2[(size_t)NQ*RCAP*2];         // exact half-scores
__device__ int   g_exa2[(size_t)NQ*RCAP*2];         // exact half argmax (absolute key)
__device__ int   g_qdis[NQ];

// ---------------------------------------------------------------------------
// Pass A: approximate scores (1-term bf16 HMMA), keys streamed by bulk DMA.
// CTA = 256 thr; tile M=128 q x N=64 keys x K=128.
// smem: Q bf16 32KB | B bf16 2x16KB | fp32 staging 32KB   (98304 B dynamic)
// ---------------------------------------------------------------------------
#define GROUPS   74
#define BBUF_OFF 32768
#define STG_OFF  65536
#define SMEM_A   98304

__global__ void __launch_bounds__(256, 2)
score_approx(const float* __restrict__ queries, const float* __restrict__ keys)
{
    extern __shared__ __align__(1024) char sm[];
    const uint32_t sb = smem_u32(sm);
    __shared__ float xv[2][128];
    __shared__ unsigned long long s_mbar;

    const int tid  = threadIdx.x;
    const int wid  = tid >> 5;
    const int lane = tid & 31;
    const int qt   = blockIdx.x & 3;
    const int rg   = blockIdx.x >> 2;
    const int q0   = qt * 128;

    const int wy = wid >> 1;
    const int wn = wid & 1;
    const int mbase = wy * 32;
    const int nbase = wn * 32;

    const uint32_t mbar = smem_u32(&s_mbar);
    if (tid == 0) MBARRIER_INIT(mbar, 1);
    __syncthreads();

    const int nrows = (NROWS - rg + GROUPS - 1) / GROUPS;
    const int NT = nrows * 4;

    // issue DMA for tile 0 (overlaps Q prologue)
    if (tid == 0) {
        MBARRIER_EXPECT_TX(mbar, 32768);
        bulk_g2s(sb + STG_OFF, keys + (size_t)rg * VPR * DIM, 32768, mbar);
    }

    // ---- Q prologue: fp32 -> bf16 -> swizzled smem ----
    {
        int q = tid >> 1, h = tid & 1;
        const float4* qp = reinterpret_cast<const float4*>(
            queries + (size_t)(q0 + q) * DIM + h * 64);
        #pragma unroll
        for (int jj = 0; jj < 8; ++jj) {
            float4 x = qp[2*jj], y = qp[2*jj+1];
            uint4 s0;
            s0.x = pack_bf16x2(x.x, x.y);
            s0.y = pack_bf16x2(x.z, x.w);
            s0.z = pack_bf16x2(y.x, y.y);
            s0.w = pack_bf16x2(y.z, y.w);
            int cb = h * 8 + jj;
            uint32_t o = (uint32_t)q * 256u + (uint32_t)((cb ^ (q & 7)) << 4);
            *reinterpret_cast<uint4*>(sm + o) = s0;
        }
    }

    // convert mapping: key cvn = tid>>2 (0..63), 128B part cvp = tid&3, bank rotation
    const int cvn = tid >> 2;
    const int cvp = tid & 3;
    const int rot = tid & 7;
    const uint32_t stg4 = (uint32_t)cvn * 32u + (uint32_t)cvp * 8u;   // float4 index base
    const uint32_t drow = (uint32_t)cvn * 256u;
    const uint32_t dxor = (uint32_t)(cvn & 7);

    // wait tile 0, convert into buf 0
    int bph = 0;
    MBARRIER_WAIT_PARITY(mbar, 0); bph = 1;
    {
        const float4* stg = reinterpret_cast<const float4*>(sm + STG_OFF);
        #pragma unroll
        for (int jj = 0; jj < 8; ++jj) {
            int m = jj ^ rot;
            int f = cvp * 8 + m;                 // float4 index within key row (0..31)
            float4 v = stg[stg4 + m];
            uint2 s; s.x = pack_bf16x2(v.x, v.y); s.y = pack_bf16x2(v.z, v.w);
            uint32_t o = drow + (uint32_t)((((uint32_t)(f >> 1)) ^ dxor) << 4) + (uint32_t)(f & 1) * 8u;
            *reinterpret_cast<uint2*>(sm + BBUF_OFF + o) = s;
        }
    }
    __syncthreads();
    if (tid == 0 && NT > 1) {
        int row1 = rg + GROUPS * (1 >> 2);
        MBARRIER_EXPECT_TX(mbar, 32768);
        bulk_g2s(sb + STG_OFF, keys + ((size_t)row1 * VPR + (size_t)(1 & 3) * 64) * DIM, 32768, mbar);
    }

    // ldmatrix lane invariants
    const uint32_t aoff = (uint32_t)(mbase + (lane & 15)) * 256u;
    const uint32_t boff = (uint32_t)(nbase + ((lane & 7) | ((lane >> 4) << 3))) * 256u;
    const int axor = lane & 7;
    const int acq  = lane >> 4;
    const int bcq  = (lane >> 3) & 1;

    // hoist A fragments for kp 0..3 (Q resident)
    uint32_t aH[4][2][4];
    #pragma unroll
    for (int kp = 0; kp < 4; ++kp) {
        const uint32_t aswz = (uint32_t)(((kp * 2 + acq) ^ axor) << 4);
        #pragma unroll
        for (int mt = 0; mt < 2; ++mt)
            LDSM_X4(aH[kp][mt][0], aH[kp][mt][1], aH[kp][mt][2], aH[kp][mt][3],
                    sb + aoff + (uint32_t)mt * 4096u + aswz);
    }

    float run_v[4];

    for (int tt = 0; tt < NT; ++tt) {
        const int row = rg + GROUPS * (tt >> 2);
        const int qtr = tt & 3;
        const int buf = tt & 1;

        // ---- compute on buf ----
        float acc[2][4][4];
        #pragma unroll
        for (int mt = 0; mt < 2; ++mt)
            #pragma unroll
            for (int nt = 0; nt < 4; ++nt)
                #pragma unroll
                for (int r = 0; r < 4; ++r) acc[mt][nt][r] = 0.f;

        const uint32_t bbase = sb + BBUF_OFF + (uint32_t)buf * 16384u;

        #pragma unroll
        for (int kp = 0; kp < 8; ++kp) {
            uint32_t ac[2][4], b[4][2];
            if (kp >= 4) {
                const uint32_t aswz = (uint32_t)(((kp * 2 + acq) ^ axor) << 4);
                #pragma unroll
                for (int mt = 0; mt < 2; ++mt)
                    LDSM_X4(ac[mt][0], ac[mt][1], ac[mt][2], ac[mt][3],
                            sb + aoff + (uint32_t)mt * 4096u + aswz);
            } else {
                #pragma unroll
                for (int mt = 0; mt < 2; ++mt)
                    #pragma unroll
                    for (int r = 0; r < 4; ++r) ac[mt][r] = aH[kp][mt][r];
            }
            const uint32_t bswz = (uint32_t)(((kp * 2 + bcq) ^ axor) << 4);
            #pragma unroll
            for (int h = 0; h < 2; ++h) {
                uint32_t r0, r1, r2, r3;
                LDSM_X4(r0, r1, r2, r3, bbase + boff + (uint32_t)h * 4096u + bswz);
                b[2*h  ][0] = r0; b[2*h  ][1] = r1;
                b[2*h+1][0] = r2; b[2*h+1][1] = r3;
            }
            #pragma unroll
            for (int mt = 0; mt < 2; ++mt)
                #pragma unroll
                for (int nt = 0; nt < 4; ++nt)
                    MMA16816(acc[mt][nt], ac[mt], b[nt]);
        }

        // ---- pipeline: wait DMA(t+1), convert to other buf, issue DMA(t+2) ----
        if (tt + 1 < NT) {
            MBARRIER_WAIT_PARITY(mbar, bph); bph ^= 1;
            const float4* stg = reinterpret_cast<const float4*>(sm + STG_OFF);
            char* bb = sm + BBUF_OFF + ((buf ^ 1) * 16384);
            #pragma unroll
            for (int jj = 0; jj < 8; ++jj) {
                int m = jj ^ rot;
                int f = cvp * 8 + m;
                float4 v = stg[stg4 + m];
                uint2 s; s.x = pack_bf16x2(v.x, v.y); s.y = pack_bf16x2(v.z, v.w);
                uint32_t o = drow + (uint32_t)((((uint32_t)(f >> 1)) ^ dxor) << 4) + (uint32_t)(f & 1) * 8u;
                *reinterpret_cast<uint2*>(bb + o) = s;
            }
            __syncthreads();
            if (tid == 0 && tt + 2 < NT) {
                int t2 = tt + 2;
                int row2 = rg + GROUPS * (t2 >> 2);
                MBARRIER_EXPECT_TX(mbar, 32768);
                bulk_g2s(sb + STG_OFF, keys + ((size_t)row2 * VPR + (size_t)(t2 & 3) * 64) * DIM,
                         32768, mbar);
            }
        }

        // ---- epilogue: per-query running max over this tile's 64 keys ----
        #pragma unroll
        for (int mt = 0; mt < 2; ++mt) {
            #pragma unroll
            for (int rh = 0; rh < 2; ++rh) {
                const int sl = mt * 2 + rh;
                float v = -3.4e38f;
                #pragma unroll
                for (int nt = 0; nt < 4; ++nt) {
                    v = fmaxf(v, acc[mt][nt][rh * 2 + 0]);
                    v = fmaxf(v, acc[mt][nt][rh * 2 + 1]);
                }
                v = fmaxf(v, __shfl_xor_sync(0xffffffffu, v, 1));
                v = fmaxf(v, __shfl_xor_sync(0xffffffffu, v, 2));
                if (qtr == 0) run_v[sl] = v;
                else          run_v[sl] = fmaxf(run_v[sl], v);
            }
        }

        if (qtr == 3) {
            if ((lane & 3) == 0) {
                #pragma unroll
                for (int mt = 0; mt < 2; ++mt)
                    #pragma unroll
                    for (int rh = 0; rh < 2; ++rh) {
                        int r = mbase + mt * 16 + rh * 8 + (lane >> 2);
                        xv[wn][r] = run_v[mt * 2 + rh];
                    }
            }
            __syncthreads();
            if (tid < 128)
                g_rowmax[(size_t)(q0 + tid) * NROWS + row] = fmaxf(xv[0][tid], xv[1][tid]);
            __syncthreads();
        }
    }
}

// ---------------------------------------------------------------------------
// Pass A2: threshold select — collect superset of top-64 rows per query.
// 8192-bin histogram over orderable float bits, suffix scan, collect >= bin.
// ---------------------------------------------------------------------------
__global__ void __launch_bounds__(256)
topsel_kernel()
{
    extern __shared__ uint32_t hist[];          // 8192 bins (32KB)
    __shared__ int csum[256];
    __shared__ int s_binB;
    __shared__ int s_cc;

    const int q = blockIdx.x, tid = threadIdx.x;
    const float* src = g_rowmax + (size_t)q * NROWS;

    for (int i = tid; i < 8192; i += 256) hist[i] = 0;
    __syncthreads();

    for (int r = tid; r < NROWS; r += 256)
        atomicAdd(&hist[ford(src[r]) >> 19], 1u);
    __syncthreads();

    // descending suffix: thread t owns desc chunk [32t, 32t+32)
    int local = 0;
    #pragma unroll
    for (int k = 0; k < 32; ++k) local += (int)hist[8191 - (32 * tid + k)];
    csum[tid] = local;
    __syncthreads();
    for (int off = 1; off < 256; off <<= 1) {
        int v = (tid >= off) ? csum[tid - off] : 0;
        __syncthreads();
        csum[tid] += v;
        __syncthreads();
    }
    int incl = csum[tid];
    int excl = incl - local;
    if (excl < 64 && incl >= 64) {
        int c = excl;
        for (int k = 0; k < 32; ++k) {
            c += (int)hist[8191 - (32 * tid + k)];
            if (c >= 64) { s_binB = 8191 - (32 * tid + k); break; }
        }
    }
    if (tid == 0) s_cc = 0;
    __syncthreads();

    const uint32_t binB = (uint32_t)s_binB;
    for (int r = tid; r < NROWS; r += 256) {
        if ((ford(src[r]) >> 19) >= binB) {
            int p = atomicAdd(&s_cc, 1);
            if (p < RCAP) g_cand[(size_t)q * RCAP + p] = r;
        }
    }
    __syncthreads();
    if (tid == 0) g_qcnt[q] = min(s_cc, RCAP);
}

// ---------------------------------------------------------------------------
// zero counters + scatter candidates into per-row query lists
// ---------------------------------------------------------------------------
__global__ void zero_kernel()
{
    int i = blockIdx.x * 256 + threadIdx.x;
    if (i < NROWS) g_rowcnt[i] = 0;
}

__global__ void __launch_bounds__(256)
scatter_kernel()
{
    const int q = blockIdx.x, slot = threadIdx.x;
    if (slot < g_qcnt[q]) {
        int row = g_cand[(size_t)q * RCAP + slot];
        int idx = atomicAdd(&g_rowcnt[row], 1);
        g_rowlist[(size_t)row * NQ + idx] = (q << 8) | slot;
    }
}

// ---------------------------------------------------------------------------
// Pass B: exact fp32 rescore. 2 CTAs per row (128 keys each, bulk-DMA'd to
// smem), warp-cooperative dots, per-(q,row,half) max+argmax.
// ---------------------------------------------------------------------------
#define SMEM_R 65536

__global__ void __launch_bounds__(256)
rescore_kernel(const float* __restrict__ queries, const float* __restrict__ keys)
{
    const int row = blockIdx.x >> 1;
    const int h   = blockIdx.x & 1;
    const int cnt = g_rowcnt[row];
    if (cnt == 0) return;

    extern __shared__ __align__(1024) float Ks[];   // [128][128] fp32, linear
    __shared__ unsigned long long red[8];
    __shared__ unsigned long long s_mbar;

    const int tid  = threadIdx.x;
    const int lane = tid & 31;
    const int w    = tid >> 5;

    const uint32_t mbar = smem_u32(&s_mbar);
    if (tid == 0) MBARRIER_INIT(mbar, 1);
    __syncthreads();
    if (tid == 0) {
        MBARRIER_EXPECT_TX(mbar, 65536);
        bulk_g2s(smem_u32(Ks), keys + ((size_t)row * VPR + (size_t)h * 128) * DIM, 65536, mbar);
    }
    MBARRIER_WAIT_PARITY(mbar, 0);

    for (int i = 0; i < cnt; ++i) {
        const int e = g_rowlist[(size_t)row * NQ + i];
        const int q = e >> 8, slot = e & 255;

        float4 qv = *reinterpret_cast<const float4*>(queries + (size_t)q * DIM + lane * 4);

        unsigned long long best = 0ull;
        #pragma unroll 4
        for (int j = 0; j < 16; ++j) {
            int kl = w * 16 + j;
            float4 kv = *reinterpret_cast<const float4*>(Ks + (size_t)kl * DIM + lane * 4);
            float d = qv.x * kv.x;
            d = fmaf(qv.y, kv.y, d);
            d = fmaf(qv.z, kv.z, d);
            d = fmaf(qv.w, kv.w, d);
            #pragma unroll
            for (int o = 16; o > 0; o >>= 1) d += __shfl_xor_sync(0xffffffffu, d, o);
            int gk = h * 128 + kl;
            unsigned long long p = ((unsigned long long)ford(d) << 32) | (uint32_t)(~gk);
            if (p > best) best = p;            // ascending gk -> tie keeps lowest
        }
        if (lane == 0) red[w] = best;
        __syncthreads();
        if (tid == 0) {
            unsigned long long b = red[0];
            #pragma unroll
            for (int ww = 1; ww < 8; ++ww) if (red[ww] > b) b = red[ww];
            size_t o = ((size_t)q * RCAP + slot) * 2 + h;
            g_exs2[o] = funord((uint32_t)(b >> 32));
            g_exa2[o] = (int)((uint8_t)(~(uint32_t)b));
        }
        __syncthreads();
    }
}

// ---------------------------------------------------------------------------
// Pass C: merge halves, exact top-32, mask/softmax/gather outputs.
// ---------------------------------------------------------------------------
__device__ __forceinline__ void put(float* out, long long off, long long lim, float v) {
    if (off < lim) out[off] = v;
}

__global__ void __launch_bounds__(128)
finalize_kernel(const float* __restrict__ values, const int* __restrict__ mem_ids,
                const int* __restrict__ ent_ids, const int* __restrict__ text_ids,
                float* __restrict__ out, long long lim)
{
    volatile __shared__ float cs[RCAP];
    __shared__ int   cm[RCAP];     // (row<<8)|slot
    __shared__ int   ca[RCAP];     // merged argmax key (absolute)
    __shared__ int   ssel[KSEL];
    __shared__ float ssc[KSEL];
    __shared__ int   sid[KSEL];

    const int q = blockIdx.x, tid = threadIdx.x;
    const int cnt = g_qcnt[q];

    for (int s = tid; s < cnt; s += 128) {
        size_t o = ((size_t)q * RCAP + s) * 2;
        float s0 = g_exs2[o], s1 = g_exs2[o + 1];
        int   a0 = g_exa2[o], a1 = g_exa2[o + 1];
        // h1 keys all > h0 keys, so tie (s1==s0) -> h0 (lower key) matches argmax
        float sc; int aa;
        if (s1 > s0) { sc = s1; aa = a1; } else { sc = s0; aa = a0; }
        cs[s] = sc;
        ca[s] = aa;
        cm[s] = (g_cand[(size_t)q * RCAP + s] << 8) | s;
    }
    __syncthreads();

    if (tid < 32) {   // warp 0: 32 selection rounds over up to 256 candidates
        for (int it = 0; it < KSEL; ++it) {
            float bv = -3.4e38f; int bm = 0x7FFFFFFF;
            #pragma unroll
            for (int k = 0; k < 8; ++k) {
                int s = tid + 32 * k;
                if (s < cnt) {
                    float v = cs[s]; int m = cm[s];
                    if (v > bv || (v == bv && m < bm)) { bv = v; bm = m; }
                }
            }
            #pragma unroll
            for (int o = 16; o > 0; o >>= 1) {
                float v2 = __shfl_xor_sync(0xffffffffu, bv, o);
                int   m2 = __shfl_xor_sync(0xffffffffu, bm, o);
                if (v2 > bv || (v2 == bv && m2 < bm)) { bv = v2; bm = m2; }
            }
            if (tid == 0) { ssel[it] = bm; ssc[it] = bv; cs[bm & 255] = -3.4e38f; }
            __syncwarp();
        }
    }
    __syncthreads();

    if (tid < KSEL) {
        int meta = ssel[tid];
        int slot = meta & 255, row = meta >> 8;
        float sc = ssc[tid];
        int   id = row * VPR + ca[slot];
        sid[tid] = id;

        int   m  = (mem_ids[id] == text_ids[q]) ? 1 : 0;
        float ms = sc - (float)m * 1e10f;

        float mx = ms;
        #pragma unroll
        for (int o = 16; o > 0; o >>= 1) mx = fmaxf(mx, __shfl_xor_sync(0xffffffffu, mx, o));
        float e = expf(ms - mx);
        float ssum = e;
        #pragma unroll
        for (int o = 16; o > 0; o >>= 1) ssum += __shfl_xor_sync(0xffffffffu, ssum, o);
        float wgt = e / ssum;

        int cdis = m;
        #pragma unroll
        for (int o = 16; o > 0; o >>= 1) cdis += __shfl_xor_sync(0xffffffffu, cdis, o);
        if (tid == 0) g_qdis[q] = cdis;

        long long base = (long long)q * KSEL + tid;
        put(out, OFF_ENT  + base, lim, (float)ent_ids[id]);
        put(out, OFF_GID  + base, lim, (float)id);
        put(out, OFF_SC   + base, lim, sc);
        put(out, OFF_MASK + base, lim, (float)m);
        put(out, OFF_ATTN + base, lim, wgt);
    }
    __syncthreads();

    for (int j = 0; j < KSEL; ++j) {
        int id = sid[j];
        long long o = OFF_VAL + ((long long)(q * KSEL + j)) * DIM + tid;
        if (o < lim) out[o] = values[(size_t)id * DIM + tid];
    }
}

// ---------------------------------------------------------------------------
// Pass D: n_disallowed scalar
// ---------------------------------------------------------------------------
__global__ void __launch_bounds__(512)
ndis_kernel(float* __restrict__ out, long long lim)
{
    __shared__ int s[512];
    int t = threadIdx.x;
    s[t] = g_qdis[t];
    __syncthreads();
    for (int st = 256; st > 0; st >>= 1) {
        if (t < st) s[t] += s[t + st];
        __syncthreads();
    }
    if (t == 0 && OFF_NDIS < lim) out[OFF_NDIS] = (float)s[0];
}

// ---------------------------------------------------------------------------
extern "C" void kernel_launch(void* const* d_in, const int* in_sizes, int n_in,
                              void* d_out, int out_size)
{
    const float* queries  = (const float*)d_in[0];
    const float* keys     = (const float*)d_in[1];
    const int*   mem_ids  = (const int*)d_in[2];
    const int*   ent_ids  = (const int*)d_in[3];
    const float* values   = (const float*)d_in[4];
    const int*   text_ids = (const int*)d_in[5];
    float* out = (float*)d_out;
    long long lim = (long long)out_size;

    cudaFuncSetAttribute(score_approx,   cudaFuncAttributeMaxDynamicSharedMemorySize, SMEM_A);
    cudaFuncSetAttribute(rescore_kernel, cudaFuncAttributeMaxDynamicSharedMemorySize, SMEM_R);
    cudaFuncSetAttribute(topsel_kernel,  cudaFuncAttributeMaxDynamicSharedMemorySize, 8192 * 4);

    score_approx<<<4 * GROUPS, 256, SMEM_A>>>(queries, keys);
    topsel_kernel<<<NQ, 256, 8192 * 4>>>();
    zero_kernel<<<(NROWS + 255) / 256, 256>>>();
    scatter_kernel<<<NQ, 256>>>();
    rescore_kernel<<<2 * NROWS, 256, SMEM_R>>>(queries, keys);
    finalize_kernel<<<NQ, 128>>>(values, mem_ids, ent_ids, text_ids, out, lim);
    ndis_kernel<<<1, 512>>>(out, lim);
}